// round 14
// baseline (speedup 1.0000x reference)
#include <cuda_runtime.h>
#include <cuda_fp16.h>
#include <math.h>
#include <stdint.h>

// ---------------- geometry ----------------
#define BB     32
#define CCH    3
#define IMG    224
#define PTCH   16
#define EE     768
#define NH     12
#define NL     12
#define NPR    16
#define NP     197
#define SS     213
#define HD     64
#define FFD    3072
#define EPSV   1e-6f
#define SCALEV 0.125f

#define BSC     (BB * NP)          // 6304 compact rows (no prompt rows)
#define MQKV    (BSC + NPR)        // 6320 rows for qkv GEMM (16 prompt rows appended)
#define NPATCH  196
#define MCONV   (BB * NPATCH)      // 6272
#define PLN     ((size_t)BB * NH * NP * HD)   // halfs per compact q/k/v plane

// ---------------- scratch (device globals: allowed) ----------------
__device__ float  g_h  [(size_t)BSC * EE];         // fp32 residual (compact)
__device__ __half g_hh [(size_t)MQKV * EE];        // LN out (+16 prompt rows)
__device__ __half g_qp [PLN];                      // Q plane
__device__ __half g_kp [PLN];                      // K plane
__device__ __half g_vp [PLN];                      // V plane
__device__ __half g_kpr[NH * NPR * HD];            // prompt K (per layer)
__device__ __half g_vpr[NH * NPR * HD];            // prompt V (per layer)
__device__ __half g_oh [(size_t)BSC * EE];         // attention out (half)
__device__ __half g_ffh[(size_t)MCONV * EE > (size_t)BSC * FFD
                        ? (size_t)MCONV * EE : (size_t)BSC * FFD];
__device__ float  g_o  [(size_t)MCONV * EE];       // conv out (fp32)
// fp16 weight copies
__device__ __half g_wq [(size_t)NL * 3 * EE * EE];
__device__ __half g_wp [(size_t)NL * EE * EE];
__device__ __half g_w1 [(size_t)NL * FFD * EE];
__device__ __half g_w2 [(size_t)NL * EE * FFD];
__device__ __half g_wc [(size_t)EE * EE];

// ---------------- helpers ----------------
__device__ __forceinline__ float blk_sum(float v) {
    __shared__ float red[8];
    __shared__ float tot;
    int lane = threadIdx.x & 31, w = threadIdx.x >> 5;
#pragma unroll
    for (int o = 16; o; o >>= 1) v += __shfl_xor_sync(0xffffffffu, v, o);
    if (lane == 0) red[w] = v;
    __syncthreads();
    if (w == 0) {
        float t = (lane < 8) ? red[lane] : 0.f;
#pragma unroll
        for (int o = 4; o; o >>= 1) t += __shfl_xor_sync(0xffffffffu, t, o);
        if (lane == 0) tot = t;
    }
    __syncthreads();
    return tot;
}

__device__ __forceinline__ void cpa16_s(uint32_t dst, const void* src, int srcBytes) {
    asm volatile("cp.async.cg.shared.global [%0], [%1], 16, %2;"
                 :: "r"(dst), "l"(src), "r"(srcBytes));
}

__device__ __forceinline__ void ldsm4(uint32_t* d, uint32_t addr) {
    asm volatile("ldmatrix.sync.aligned.m8n8.x4.shared.b16 {%0,%1,%2,%3}, [%4];"
                 : "=r"(d[0]), "=r"(d[1]), "=r"(d[2]), "=r"(d[3]) : "r"(addr));
}

__device__ __forceinline__ void ldsm4t(uint32_t* d, uint32_t addr) {
    asm volatile("ldmatrix.sync.aligned.m8n8.x4.trans.shared.b16 {%0,%1,%2,%3}, [%4];"
                 : "=r"(d[0]), "=r"(d[1]), "=r"(d[2]), "=r"(d[3]) : "r"(addr));
}

__device__ __forceinline__ void mma16816(float* d, const uint32_t* a, const uint32_t* b) {
    asm volatile(
        "mma.sync.aligned.m16n8k16.row.col.f32.f16.f16.f32 "
        "{%0,%1,%2,%3}, {%4,%5,%6,%7}, {%8,%9}, {%0,%1,%2,%3};"
        : "+f"(d[0]), "+f"(d[1]), "+f"(d[2]), "+f"(d[3])
        : "r"(a[0]), "r"(a[1]), "r"(a[2]), "r"(a[3]), "r"(b[0]), "r"(b[1]));
}

// ---------------- weight fp16 convert ----------------
__global__ void cvt_kernel(const float* __restrict__ src, __half* __restrict__ dst, int n4) {
    int i = blockIdx.x * 256 + threadIdx.x;
    if (i >= n4) return;
    float4 v = ((const float4*)src)[i];
    ((__half2*)dst)[2 * i]     = __floats2half2_rn(v.x, v.y);
    ((__half2*)dst)[2 * i + 1] = __floats2half2_rn(v.z, v.w);
}

// ---------------- im2col (half out) ----------------
__global__ void im2col_kernel(const float* __restrict__ x, __half* __restrict__ out) {
    int idx = blockIdx.x * 256 + threadIdx.x;
    if (idx >= MCONV * EE) return;
    int m = idx / EE;
    int k = idx % EE;
    int b = m / NPATCH, p = m % NPATCH;
    int c = k >> 8, rem = k & 255, i = rem >> 4, j = rem & 15;
    int py = p / 14, px = p % 14;
    out[idx] = __float2half_rn(
        x[(((size_t)b * CCH + c) * IMG + (py * PTCH + i)) * IMG + (px * PTCH + j)]);
}

// ---------------- FP16 tensor GEMM (mma.sync m16n8k16 + ldmatrix) ----------
// epi 0: fp32 out ; epi 1: bias+GELU -> half ; epi 2: bias+residual fp32 ;
// epi 4: bias -> half, qkv compact planes + prompt K/V buffers
#define KT        64
#define RSB       144
#define MAT_BYTES (128 * RSB)
#define STG_BYTES (2 * MAT_BYTES)
#define NSTAGE    3
#define TG_SMEM   (NSTAGE * STG_BYTES)

__global__ __launch_bounds__(256)
void hgemm_kernel(const __half* __restrict__ A, const __half* __restrict__ Bw,
                  const float* __restrict__ bias, float* __restrict__ Cf,
                  __half* __restrict__ Ch, __half* __restrict__ Ch2,
                  __half* __restrict__ Ch3, __half* __restrict__ Ch4,
                  __half* __restrict__ Ch5, int M, int N, int K, int epi)
{
    extern __shared__ char smg[];
    const uint32_t smem_base = (uint32_t)__cvta_generic_to_shared(smg);
    const int tid  = threadIdx.x;
    const int warp = tid >> 5, lane = tid & 31;
    const int wm = warp >> 2;
    const int wn = warp & 3;
    const int r  = lane >> 2;
    const int cg = lane & 3;
    const int row0 = blockIdx.y * 128;
    const int col0 = blockIdx.x * 128;

    const int lg = lane >> 3;
    const int lt = lane & 7;

    float acc[4][4][4];
#pragma unroll
    for (int mi = 0; mi < 4; mi++)
#pragma unroll
        for (int ni = 0; ni < 4; ni++)
#pragma unroll
            for (int e = 0; e < 4; e++) acc[mi][ni][e] = 0.f;

    const int frow   = tid >> 3;
    const int fcol16 = tid & 7;
    const int nc = K / KT;

#define FILL(sidx, kk0)                                                          \
    {                                                                            \
        uint32_t sA = smem_base + (sidx) * STG_BYTES;                            \
        uint32_t sB = sA + MAT_BYTES;                                            \
        _Pragma("unroll")                                                        \
        for (int c = 0; c < 4; c++) {                                            \
            int row = frow + c * 32;                                             \
            uint32_t doff = (uint32_t)row * RSB + fcol16 * 16;                   \
            cpa16_s(sA + doff, A + (size_t)(row0 + row) * K + (kk0) + fcol16 * 8,\
                    (row0 + row < M) ? 16 : 0);                                  \
            cpa16_s(sB + doff, Bw + (size_t)(col0 + row) * K + (kk0) + fcol16 * 8, 16);\
        }                                                                        \
        asm volatile("cp.async.commit_group;");                                  \
    }

    FILL(0, 0);
    if (nc > 1) FILL(1, KT);

    for (int i = 0; i < nc; i++) {
        if (i + 1 < nc) {
            asm volatile("cp.async.wait_group 1;");
        } else {
            asm volatile("cp.async.wait_group 0;");
        }
        __syncthreads();
        if (i + 2 < nc) FILL((i + 2) % NSTAGE, (i + 2) * KT);

        const uint32_t sA = smem_base + (i % NSTAGE) * STG_BYTES;
        const uint32_t sB = sA + MAT_BYTES;
#pragma unroll
        for (int kk = 0; kk < KT; kk += 16) {
            uint32_t af[4][4], bB[2][4];
#pragma unroll
            for (int mi = 0; mi < 4; mi++) {
                uint32_t addr = sA
                    + (uint32_t)(wm * 64 + mi * 16 + (lg & 1) * 8 + lt) * RSB
                    + (kk + (lg >> 1) * 8) * 2;
                ldsm4(af[mi], addr);
            }
#pragma unroll
            for (int ni2 = 0; ni2 < 2; ni2++) {
                uint32_t addr = sB
                    + (uint32_t)(wn * 32 + ni2 * 16 + (lg >> 1) * 8 + lt) * RSB
                    + (kk + (lg & 1) * 8) * 2;
                ldsm4(bB[ni2], addr);
            }
#pragma unroll
            for (int mi = 0; mi < 4; mi++)
#pragma unroll
                for (int ni = 0; ni < 4; ni++)
                    mma16816(acc[mi][ni], af[mi], &bB[ni >> 1][(ni & 1) * 2]);
        }
    }
#undef FILL

#pragma unroll
    for (int mi = 0; mi < 4; mi++) {
        int mr0 = row0 + wm * 64 + mi * 16 + r;
#pragma unroll
        for (int ni = 0; ni < 4; ni++) {
            int nc2 = col0 + wn * 32 + ni * 8 + 2 * cg;
            float b0 = bias[nc2], b1 = bias[nc2 + 1];
#pragma unroll
            for (int half_ = 0; half_ < 2; half_++) {
                int rr = mr0 + half_ * 8;
                if (rr >= M) continue;
                float v0 = acc[mi][ni][half_ * 2 + 0] + b0;
                float v1 = acc[mi][ni][half_ * 2 + 1] + b1;
                size_t idx = (size_t)rr * N + nc2;
                if (epi == 1) {
                    v0 = 0.5f * v0 * (1.f + erff(v0 * 0.70710678118654752f));
                    v1 = 0.5f * v1 * (1.f + erff(v1 * 0.70710678118654752f));
                    *(__half2*)&Ch[idx] = __floats2half2_rn(v0, v1);
                } else if (epi == 4) {
                    // Ch=qp, Ch2=kp, Ch3=vp, Ch4=kpr, Ch5=vpr
                    int p = nc2 / EE, e = nc2 - p * EE;
                    int hh = e >> 6, d = e & 63;
                    __half2 hv = __floats2half2_rn(v0, v1);
                    if (rr < BSC) {
                        int b = rr / NP, s = rr - b * NP;
                        __half* pl = (p == 0) ? Ch : (p == 1) ? Ch2 : Ch3;
                        *(__half2*)(pl + ((size_t)(b * NH + hh) * NP + s) * HD + d) = hv;
                    } else if (p >= 1) {
                        int sp = rr - BSC;   // 0..15
                        __half* pl = (p == 1) ? Ch4 : Ch5;
                        *(__half2*)(pl + (size_t)(hh * NPR + sp) * HD + d) = hv;
                    }
                } else {
                    if (epi == 2) { v0 += Cf[idx]; v1 += Cf[idx + 1]; }
                    Cf[idx] = v0; Cf[idx + 1] = v1;
                }
            }
        }
    }
}

// ---------------- LN pre (cls/pos assembly; fp32 out, compact) --------------
__global__ void lnpre_kernel(const float* __restrict__ conv, const float* __restrict__ cls,
                             const float* __restrict__ pos, const float* __restrict__ g,
                             const float* __restrict__ bb, float* __restrict__ dst)
{
    int row = blockIdx.x;              // b*NP + s
    int b = row / NP, s = row % NP;
    int t = threadIdx.x;
    const float* base = (s == 0) ? cls : conv + (size_t)(b * NPATCH + s - 1) * EE;
    const float* pr = pos + (size_t)s * EE;
    float x0 = base[t] + pr[t];
    float x1 = base[t + 256] + pr[t + 256];
    float x2 = base[t + 512] + pr[t + 512];
    float mean = blk_sum(x0 + x1 + x2) * (1.f / EE);
    float d0 = x0 - mean, d1 = x1 - mean, d2 = x2 - mean;
    float var = blk_sum(d0 * d0 + d1 * d1 + d2 * d2) * (1.f / EE);
    float rs = rsqrtf(var + EPSV);
    float* o = dst + (size_t)row * EE;
    o[t]       = d0 * rs * g[t]       + bb[t];
    o[t + 256] = d1 * rs * g[t + 256] + bb[t + 256];
    o[t + 512] = d2 * rs * g[t + 512] + bb[t + 512];
}

// ---------------- LN warp-per-row (half out) ----------------
// nrows must be multiple of 8 handled by caller grid; guard inside.
__global__ __launch_bounds__(256)
void lnw_kernel(const float* __restrict__ src, const float* __restrict__ g,
                const float* __restrict__ bb, __half* __restrict__ dst, int nrows)
{
    int ww = threadIdx.x >> 5, lane = threadIdx.x & 31;
    int row = blockIdx.x * 8 + ww;
    if (row >= nrows) return;
    const float* in = src + (size_t)row * EE;
    float4 v[6];
    float sum = 0.f;
#pragma unroll
    for (int j = 0; j < 6; j++) {
        v[j] = *(const float4*)(in + j * 128 + lane * 4);
        sum += v[j].x + v[j].y + v[j].z + v[j].w;
    }
#pragma unroll
    for (int o = 16; o; o >>= 1) sum += __shfl_xor_sync(0xffffffffu, sum, o);
    float mean = sum * (1.f / EE);
    float var = 0.f;
#pragma unroll
    for (int j = 0; j < 6; j++) {
        float a = v[j].x - mean, b2 = v[j].y - mean;
        float c = v[j].z - mean, d = v[j].w - mean;
        var += a * a + b2 * b2 + c * c + d * d;
    }
#pragma unroll
    for (int o = 16; o; o >>= 1) var += __shfl_xor_sync(0xffffffffu, var, o);
    float rs = rsqrtf(var * (1.f / EE) + EPSV);
    __half* op = dst + (size_t)row * EE;
#pragma unroll
    for (int j = 0; j < 6; j++) {
        int e = j * 128 + lane * 4;
        float4 gv = *(const float4*)(g + e);
        float4 bv = *(const float4*)(bb + e);
        float r0 = (v[j].x - mean) * rs * gv.x + bv.x;
        float r1 = (v[j].y - mean) * rs * gv.y + bv.y;
        float r2 = (v[j].z - mean) * rs * gv.z + bv.z;
        float r3 = (v[j].w - mean) * rs * gv.w + bv.w;
        *(__half2*)(op + e)     = __floats2half2_rn(r0, r1);
        *(__half2*)(op + e + 2) = __floats2half2_rn(r2, r3);
    }
}

// ---------------- LN post (cls only; fp32 out) ----------------
__global__ void lnpost_kernel(const float* __restrict__ src, const float* __restrict__ g,
                              const float* __restrict__ bb, float* __restrict__ dst)
{
    int b = blockIdx.x;
    int t = threadIdx.x;
    const float* in = src + (size_t)(b * NP) * EE;
    float x0 = in[t], x1 = in[t + 256], x2 = in[t + 512];
    float mean = blk_sum(x0 + x1 + x2) * (1.f / EE);
    float d0 = x0 - mean, d1 = x1 - mean, d2 = x2 - mean;
    float var = blk_sum(d0 * d0 + d1 * d1 + d2 * d2) * (1.f / EE);
    float rs = rsqrtf(var + EPSV);
    float* o = dst + (size_t)b * EE;
    o[t]       = d0 * rs * g[t]       + bb[t];
    o[t + 256] = d1 * rs * g[t + 256] + bb[t + 256];
    o[t + 512] = d2 * rs * g[t + 512] + bb[t + 512];
}

// ---------------- tensor-core flash attention (compact planes) --------------
// smem: Qv/Kv/Vv each [224][72]h (144B rows), then fac/nb [224]f each
#define ATROW 144
#define ATPL  (224 * ATROW)
#define AT_SMEM (3 * ATPL + 224 * 8)

__global__ __launch_bounds__(256)
void attn_kernel(const __half* __restrict__ qp, const __half* __restrict__ kp,
                 const __half* __restrict__ vp, const __half* __restrict__ kpr,
                 const __half* __restrict__ vpr, const float* __restrict__ coeff,
                 __half* __restrict__ outp)
{
    extern __shared__ char smraw[];
    const uint32_t smem_base = (uint32_t)__cvta_generic_to_shared(smraw);
    float* fac = (float*)(smraw + 3 * ATPL);
    float* nb  = fac + 224;

    const int bh = blockIdx.x;
    const int b = bh / NH, h = bh % NH;
    const int tid = threadIdx.x;
    const int w = tid >> 5, lane = tid & 31;
    const int r = lane >> 2, cg = lane & 3;
    const int lg = lane >> 3, lt = lane & 7;

    const size_t bhbase = (size_t)(b * NH + h) * NP * HD;

    if (tid < 224) {
        float f = 0.f, nbv = -1e30f;
        if (tid < NP)      { f = SCALEV; nbv = 0.f; }
        else if (tid < SS) { f = SCALEV * coeff[tid - NP]; nbv = 0.f; }
        fac[tid] = f; nb[tid] = nbv;
    }
    // stage Q, K, V (Q: rows<197; K/V: rows<197 from plane, 197..212 prompt, rest 0)
    for (int idx = tid; idx < 3 * 224 * 8; idx += 256) {
        int pl = idx / (224 * 8);
        int rem = idx - pl * (224 * 8);
        int s = rem >> 3, c = rem & 7;
        const __half* src;
        int bytes = 16;
        if (s < NP) {
            const __half* plane = (pl == 0) ? qp : (pl == 1) ? kp : vp;
            src = plane + bhbase + (size_t)s * HD + c * 8;
        } else if (s < SS && pl >= 1) {
            const __half* pr = (pl == 1) ? kpr : vpr;
            src = pr + (size_t)(h * NPR + (s - NP)) * HD + c * 8;
        } else {
            src = qp; bytes = 0;
        }
        cpa16_s(smem_base + pl * ATPL + s * ATROW + c * 16, src, bytes);
    }
    asm volatile("cp.async.commit_group;");
    asm volatile("cp.async.wait_group 0;");
    __syncthreads();

    const uint32_t QvU = smem_base;
    const uint32_t KvU = smem_base + ATPL;
    const uint32_t VvU = smem_base + 2 * ATPL;

    for (int q0 = w * 16; q0 < 208; q0 += 128) {
        uint32_t qf[4][4];
#pragma unroll
        for (int ks = 0; ks < 4; ks++)
            ldsm4(qf[ks], QvU + (uint32_t)(q0 + (lg & 1) * 8 + lt) * ATROW
                              + (ks * 16 + (lg >> 1) * 8) * 2);

        float m0 = -INFINITY, m1 = -INFINITY, l0 = 0.f, l1 = 0.f;
        float ao[8][4];
#pragma unroll
        for (int nt = 0; nt < 8; nt++)
#pragma unroll
            for (int e = 0; e < 4; e++) ao[nt][e] = 0.f;

        for (int kt = 0; kt < 14; kt++) {
            float sa[2][4];
#pragma unroll
            for (int ns = 0; ns < 2; ns++)
#pragma unroll
                for (int e = 0; e < 4; e++) sa[ns][e] = 0.f;

#pragma unroll
            for (int ks = 0; ks < 4; ks++) {
                uint32_t bK[4];
                ldsm4(bK, KvU + (uint32_t)(kt * 16 + (lg >> 1) * 8 + lt) * ATROW
                              + (ks * 16 + (lg & 1) * 8) * 2);
                mma16816(sa[0], qf[ks], &bK[0]);
                mma16816(sa[1], qf[ks], &bK[2]);
            }

            float p[2][4];
            float tm0 = -INFINITY, tm1 = -INFINITY;
#pragma unroll
            for (int ns = 0; ns < 2; ns++) {
                int c0 = kt * 16 + ns * 8 + 2 * cg;
                float f0 = fac[c0], f1 = fac[c0 + 1];
                float n0 = nb[c0],  n1 = nb[c0 + 1];
                sa[ns][0] = sa[ns][0] * f0 + n0;
                sa[ns][1] = sa[ns][1] * f1 + n1;
                sa[ns][2] = sa[ns][2] * f0 + n0;
                sa[ns][3] = sa[ns][3] * f1 + n1;
                tm0 = fmaxf(tm0, fmaxf(sa[ns][0], sa[ns][1]));
                tm1 = fmaxf(tm1, fmaxf(sa[ns][2], sa[ns][3]));
            }
#pragma unroll
            for (int o = 1; o <= 2; o <<= 1) {
                tm0 = fmaxf(tm0, __shfl_xor_sync(0xffffffffu, tm0, o));
                tm1 = fmaxf(tm1, __shfl_xor_sync(0xffffffffu, tm1, o));
            }
            float mn0 = fmaxf(m0, tm0), mn1 = fmaxf(m1, tm1);
            float sc0 = __expf(m0 - mn0), sc1 = __expf(m1 - mn1);
            float rs0 = 0.f, rs1 = 0.f;
#pragma unroll
            for (int ns = 0; ns < 2; ns++) {
                p[ns][0] = __expf(sa[ns][0] - mn0);
                p[ns][1] = __expf(sa[ns][1] - mn0);
                p[ns][2] = __expf(sa[ns][2] - mn1);
                p[ns][3] = __expf(sa[ns][3] - mn1);
                rs0 += p[ns][0] + p[ns][1];
                rs1 += p[ns][2] + p[ns][3];
            }
#pragma unroll
            for (int o = 1; o <= 2; o <<= 1) {
                rs0 += __shfl_xor_sync(0xffffffffu, rs0, o);
                rs1 += __shfl_xor_sync(0xffffffffu, rs1, o);
            }
            l0 = l0 * sc0 + rs0; l1 = l1 * sc1 + rs1;
            m0 = mn0; m1 = mn1;

            uint32_t pf[4];
            __half2 ph;
            ph = __floats2half2_rn(p[0][0], p[0][1]); pf[0] = *(uint32_t*)&ph;
            ph = __floats2half2_rn(p[0][2], p[0][3]); pf[1] = *(uint32_t*)&ph;
            ph = __floats2half2_rn(p[1][0], p[1][1]); pf[2] = *(uint32_t*)&ph;
            ph = __floats2half2_rn(p[1][2], p[1][3]); pf[3] = *(uint32_t*)&ph;

#pragma unroll
            for (int nt2 = 0; nt2 < 4; nt2++) {
                uint32_t vf[4];
                ldsm4t(vf, VvU + (uint32_t)(kt * 16 + (lg & 1) * 8 + lt) * ATROW
                               + (nt2 * 16 + (lg >> 1) * 8) * 2);
                int n0 = 2 * nt2, n1 = 2 * nt2 + 1;
                ao[n0][0] *= sc0; ao[n0][1] *= sc0; ao[n0][2] *= sc1; ao[n0][3] *= sc1;
                ao[n1][0] *= sc0; ao[n1][1] *= sc0; ao[n1][2] *= sc1; ao[n1][3] *= sc1;
                mma16816(ao[n0], pf, &vf[0]);
                mma16816(ao[n1], pf, &vf[2]);
            }
        }

        float inv0 = 1.f / l0, inv1 = 1.f / l1;
        int q = q0 + r;
        if (q < NP) {
            __half* orow = outp + (size_t)(b * NP + q) * EE + h * HD;
#pragma unroll
            for (int nt = 0; nt < 8; nt++)
                *(__half2*)&orow[nt * 8 + 2 * cg] =
                    __floats2half2_rn(ao[nt][0] * inv0, ao[nt][1] * inv0);
        }
        int q2 = q0 + 8 + r;
        if (q2 < NP) {
            __half* orow = outp + (size_t)(b * NP + q2) * EE + h * HD;
#pragma unroll
            for (int nt = 0; nt < 8; nt++)
                *(__half2*)&orow[nt * 8 + 2 * cg] =
                    __floats2half2_rn(ao[nt][2] * inv1, ao[nt][3] * inv1);
        }
    }
}

// ---------------- host launch ----------------
extern "C" void kernel_launch(void* const* d_in, const int* in_sizes, int n_in,
                              void* d_out, int out_size)
{
    const float* x        = (const float*)d_in[0];
    const float* coeff    = (const float*)d_in[1];
    const float* patch_w  = (const float*)d_in[2];
    const float* patch_b  = (const float*)d_in[3];
    const float* cls      = (const float*)d_in[4];
    const float* pos      = (const float*)d_in[5];
    const float* lnpre_g  = (const float*)d_in[6];
    const float* lnpre_b  = (const float*)d_in[7];
    const float* prompts  = (const float*)d_in[8];
    const float* ln1_g    = (const float*)d_in[9];
    const float* ln1_b    = (const float*)d_in[10];
    const float* qkv_w    = (const float*)d_in[11];
    const float* qkv_b    = (const float*)d_in[12];
    const float* proj_w   = (const float*)d_in[13];
    const float* proj_b   = (const float*)d_in[14];
    const float* ln2_g    = (const float*)d_in[15];
    const float* ln2_b    = (const float*)d_in[16];
    const float* fc1_w    = (const float*)d_in[17];
    const float* fc1_b    = (const float*)d_in[18];
    const float* fc2_w    = (const float*)d_in[19];
    const float* fc2_b    = (const float*)d_in[20];
    const float* lnpost_g = (const float*)d_in[21];
    const float* lnpost_b = (const float*)d_in[22];
    float* out = (float*)d_out;

    float *p_h, *p_o;
    __half *p_hh, *p_qp, *p_kp, *p_vp, *p_kpr, *p_vpr, *p_oh, *p_ffh;
    __half *p_wq, *p_wp, *p_w1, *p_w2, *p_wc;
    cudaGetSymbolAddress((void**)&p_h,   g_h);
    cudaGetSymbolAddress((void**)&p_hh,  g_hh);
    cudaGetSymbolAddress((void**)&p_qp,  g_qp);
    cudaGetSymbolAddress((void**)&p_kp,  g_kp);
    cudaGetSymbolAddress((void**)&p_vp,  g_vp);
    cudaGetSymbolAddress((void**)&p_kpr, g_kpr);
    cudaGetSymbolAddress((void**)&p_vpr, g_vpr);
    cudaGetSymbolAddress((void**)&p_oh,  g_oh);
    cudaGetSymbolAddress((void**)&p_ffh, g_ffh);
    cudaGetSymbolAddress((void**)&p_o,   g_o);
    cudaGetSymbolAddress((void**)&p_wq,  g_wq);
    cudaGetSymbolAddress((void**)&p_wp,  g_wp);
    cudaGetSymbolAddress((void**)&p_w1,  g_w1);
    cudaGetSymbolAddress((void**)&p_w2,  g_w2);
    cudaGetSymbolAddress((void**)&p_wc,  g_wc);

    cudaFuncSetAttribute(attn_kernel, cudaFuncAttributeMaxDynamicSharedMemorySize, AT_SMEM);
    cudaFuncSetAttribute(hgemm_kernel, cudaFuncAttributeMaxDynamicSharedMemorySize, TG_SMEM);

    {
        int n;
        n = NL * 3 * EE * EE / 4; cvt_kernel<<<(n + 255) / 256, 256>>>(qkv_w,  p_wq, n);
        n = NL * EE * EE / 4;     cvt_kernel<<<(n + 255) / 256, 256>>>(proj_w, p_wp, n);
        n = NL * FFD * EE / 4;    cvt_kernel<<<(n + 255) / 256, 256>>>(fc1_w,  p_w1, n);
        n = NL * EE * FFD / 4;    cvt_kernel<<<(n + 255) / 256, 256>>>(fc2_w,  p_w2, n);
        n = EE * EE / 4;          cvt_kernel<<<(n + 255) / 256, 256>>>(patch_w, p_wc, n);
    }

    im2col_kernel<<<(MCONV * EE + 255) / 256, 256>>>(x, p_ffh);
    hgemm_kernel<<<dim3(EE / 128, MCONV / 128), 256, TG_SMEM>>>(
        p_ffh, p_wc, patch_b, p_o, (__half*)0, (__half*)0, (__half*)0,
        (__half*)0, (__half*)0, MCONV, EE, EE, 0);

    lnpre_kernel<<<BB * NP, 256>>>(p_o, cls, pos, lnpre_g, lnpre_b, p_h);

    const int mt = (MQKV + 127) / 128;   // 50 (covers both 6320 and 6304)
    for (int l = 0; l < NL; l++) {
        // LN1 on compact rows + 16 prompt rows appended at g_hh[BSC..]
        lnw_kernel<<<(BSC + 7) / 8, 256>>>(p_h, ln1_g + l * EE, ln1_b + l * EE,
                                           p_hh, BSC);
        lnw_kernel<<<2, 256>>>(prompts + (size_t)l * NPR * EE,
                               ln1_g + l * EE, ln1_b + l * EE,
                               p_hh + (size_t)BSC * EE, NPR);
        hgemm_kernel<<<dim3(3 * EE / 128, mt), 256, TG_SMEM>>>(
            p_hh, p_wq + (size_t)l * 3 * EE * EE, qkv_b + (size_t)l * 3 * EE,
            (float*)0, p_qp, p_kp, p_vp, p_kpr, p_vpr, MQKV, 3 * EE, EE, 4);
        attn_kernel<<<BB * NH, 256, AT_SMEM>>>(p_qp, p_kp, p_vp, p_kpr, p_vpr,
                                               coeff + (size_t)l * NPR, p_oh);
        hgemm_kernel<<<dim3(EE / 128, mt), 256, TG_SMEM>>>(
            p_oh, p_wp + (size_t)l * EE * EE, proj_b + (size_t)l * EE,
            p_h, (__half*)0, (__half*)0, (__half*)0, (__half*)0, (__half*)0,
            BSC, EE, EE, 2);
        lnw_kernel<<<(BSC + 7) / 8, 256>>>(p_h, ln2_g + l * EE, ln2_b + l * EE,
                                           p_hh, BSC);
        hgemm_kernel<<<dim3(FFD / 128, mt), 256, TG_SMEM>>>(
            p_hh, p_w1 + (size_t)l * FFD * EE, fc1_b + (size_t)l * FFD,
            (float*)0, p_ffh, (__half*)0, (__half*)0, (__half*)0, (__half*)0,
            BSC, FFD, EE, 1);
        hgemm_kernel<<<dim3(EE / 128, mt), 256, TG_SMEM>>>(
            p_ffh, p_w2 + (size_t)l * EE * FFD, fc2_b + (size_t)l * EE,
            p_h, (__half*)0, (__half*)0, (__half*)0, (__half*)0, (__half*)0,
            BSC, EE, FFD, 2);
    }

    lnpost_kernel<<<BB, 256>>>(p_h, lnpost_g, lnpost_b, out);
}

// round 15
// speedup vs baseline: 1.0117x; 1.0117x over previous
#include <cuda_runtime.h>
#include <cuda_fp16.h>
#include <math.h>
#include <stdint.h>

// ---------------- geometry ----------------
#define BB     32
#define CCH    3
#define IMG    224
#define PTCH   16
#define EE     768
#define NH     12
#define NL     12
#define NPR    16
#define NP     197
#define SS     213
#define HD     64
#define FFD    3072
#define EPSV   1e-6f
#define SCALEV 0.125f

#define BSC     (BB * NP)          // 6304 compact rows (no prompt rows)
#define MQKV    (BSC + NPR)        // 6320 rows for qkv GEMM (16 prompt rows appended)
#define NPATCH  196
#define MCONV   (BB * NPATCH)      // 6272
#define PLN     ((size_t)BB * NH * NP * HD)   // halfs per compact q/k/v plane

// ---------------- scratch (device globals: allowed) ----------------
__device__ float  g_h  [(size_t)BSC * EE];         // fp32 residual (compact)
__device__ __half g_hh [(size_t)MQKV * EE];        // LN out (+16 prompt rows)
__device__ __half g_qp [PLN];                      // Q plane
__device__ __half g_kp [PLN];                      // K plane
__device__ __half g_vp [PLN];                      // V plane
__device__ __half g_kpr[NH * NPR * HD];            // prompt K (per layer)
__device__ __half g_vpr[NH * NPR * HD];            // prompt V (per layer)
__device__ __half g_oh [(size_t)BSC * EE];         // attention out (half)
__device__ __half g_ffh[(size_t)MCONV * EE > (size_t)BSC * FFD
                        ? (size_t)MCONV * EE : (size_t)BSC * FFD];
__device__ float  g_o  [(size_t)MCONV * EE];       // conv out (fp32)
// fp16 weight copies
__device__ __half g_wq [(size_t)NL * 3 * EE * EE];
__device__ __half g_wp [(size_t)NL * EE * EE];
__device__ __half g_w1 [(size_t)NL * FFD * EE];
__device__ __half g_w2 [(size_t)NL * EE * FFD];
__device__ __half g_wc [(size_t)EE * EE];

// ---------------- helpers ----------------
__device__ __forceinline__ float blk_sum(float v) {
    __shared__ float red[8];
    __shared__ float tot;
    int lane = threadIdx.x & 31, w = threadIdx.x >> 5;
#pragma unroll
    for (int o = 16; o; o >>= 1) v += __shfl_xor_sync(0xffffffffu, v, o);
    if (lane == 0) red[w] = v;
    __syncthreads();
    if (w == 0) {
        float t = (lane < 8) ? red[lane] : 0.f;
#pragma unroll
        for (int o = 4; o; o >>= 1) t += __shfl_xor_sync(0xffffffffu, t, o);
        if (lane == 0) tot = t;
    }
    __syncthreads();
    return tot;
}

__device__ __forceinline__ void cpa16_s(uint32_t dst, const void* src, int srcBytes) {
    asm volatile("cp.async.cg.shared.global [%0], [%1], 16, %2;"
                 :: "r"(dst), "l"(src), "r"(srcBytes));
}

__device__ __forceinline__ void ldsm4(uint32_t* d, uint32_t addr) {
    asm volatile("ldmatrix.sync.aligned.m8n8.x4.shared.b16 {%0,%1,%2,%3}, [%4];"
                 : "=r"(d[0]), "=r"(d[1]), "=r"(d[2]), "=r"(d[3]) : "r"(addr));
}

__device__ __forceinline__ void ldsm4t(uint32_t* d, uint32_t addr) {
    asm volatile("ldmatrix.sync.aligned.m8n8.x4.trans.shared.b16 {%0,%1,%2,%3}, [%4];"
                 : "=r"(d[0]), "=r"(d[1]), "=r"(d[2]), "=r"(d[3]) : "r"(addr));
}

__device__ __forceinline__ void mma16816(float* d, const uint32_t* a, const uint32_t* b) {
    asm volatile(
        "mma.sync.aligned.m16n8k16.row.col.f32.f16.f16.f32 "
        "{%0,%1,%2,%3}, {%4,%5,%6,%7}, {%8,%9}, {%0,%1,%2,%3};"
        : "+f"(d[0]), "+f"(d[1]), "+f"(d[2]), "+f"(d[3])
        : "r"(a[0]), "r"(a[1]), "r"(a[2]), "r"(a[3]), "r"(b[0]), "r"(b[1]));
}

// ---------------- weight fp16 convert ----------------
__global__ void cvt_kernel(const float* __restrict__ src, __half* __restrict__ dst, int n4) {
    int i = blockIdx.x * 256 + threadIdx.x;
    if (i >= n4) return;
    float4 v = ((const float4*)src)[i];
    ((__half2*)dst)[2 * i]     = __floats2half2_rn(v.x, v.y);
    ((__half2*)dst)[2 * i + 1] = __floats2half2_rn(v.z, v.w);
}

// ---------------- im2col (half out) ----------------
__global__ void im2col_kernel(const float* __restrict__ x, __half* __restrict__ out) {
    int idx = blockIdx.x * 256 + threadIdx.x;
    if (idx >= MCONV * EE) return;
    int m = idx / EE;
    int k = idx % EE;
    int b = m / NPATCH, p = m % NPATCH;
    int c = k >> 8, rem = k & 255, i = rem >> 4, j = rem & 15;
    int py = p / 14, px = p % 14;
    out[idx] = __float2half_rn(
        x[(((size_t)b * CCH + c) * IMG + (py * PTCH + i)) * IMG + (px * PTCH + j)]);
}

// ---------------- FP16 tensor GEMM (mma.sync m16n8k16 + ldmatrix) ----------
// epi 0: fp32 out ; epi 1: bias+GELU -> half ; epi 2: bias+residual fp32 ;
// epi 4: bias -> half, qkv compact planes + prompt K/V buffers
#define KT        64
#define RSB       144
#define MAT_BYTES (128 * RSB)
#define STG_BYTES (2 * MAT_BYTES)
#define NSTAGE    3
#define TG_SMEM   (NSTAGE * STG_BYTES)

__global__ __launch_bounds__(256)
void hgemm_kernel(const __half* __restrict__ A, const __half* __restrict__ Bw,
                  const float* __restrict__ bias, float* __restrict__ Cf,
                  __half* __restrict__ Ch, __half* __restrict__ Ch2,
                  __half* __restrict__ Ch3, __half* __restrict__ Ch4,
                  __half* __restrict__ Ch5, int M, int N, int K, int epi)
{
    extern __shared__ char smg[];
    const uint32_t smem_base = (uint32_t)__cvta_generic_to_shared(smg);
    const int tid  = threadIdx.x;
    const int warp = tid >> 5, lane = tid & 31;
    const int wm = warp >> 2;
    const int wn = warp & 3;
    const int r  = lane >> 2;
    const int cg = lane & 3;
    const int row0 = blockIdx.y * 128;
    const int col0 = blockIdx.x * 128;

    const int lg = lane >> 3;
    const int lt = lane & 7;

    float acc[4][4][4];
#pragma unroll
    for (int mi = 0; mi < 4; mi++)
#pragma unroll
        for (int ni = 0; ni < 4; ni++)
#pragma unroll
            for (int e = 0; e < 4; e++) acc[mi][ni][e] = 0.f;

    const int frow   = tid >> 3;
    const int fcol16 = tid & 7;
    const int nc = K / KT;

#define FILL(sidx, kk0)                                                          \
    {                                                                            \
        uint32_t sA = smem_base + (sidx) * STG_BYTES;                            \
        uint32_t sB = sA + MAT_BYTES;                                            \
        _Pragma("unroll")                                                        \
        for (int c = 0; c < 4; c++) {                                            \
            int row = frow + c * 32;                                             \
            uint32_t doff = (uint32_t)row * RSB + fcol16 * 16;                   \
            cpa16_s(sA + doff, A + (size_t)(row0 + row) * K + (kk0) + fcol16 * 8,\
                    (row0 + row < M) ? 16 : 0);                                  \
            cpa16_s(sB + doff, Bw + (size_t)(col0 + row) * K + (kk0) + fcol16 * 8, 16);\
        }                                                                        \
        asm volatile("cp.async.commit_group;");                                  \
    }

    FILL(0, 0);
    if (nc > 1) FILL(1, KT);

    for (int i = 0; i < nc; i++) {
        if (i + 1 < nc) {
            asm volatile("cp.async.wait_group 1;");
        } else {
            asm volatile("cp.async.wait_group 0;");
        }
        __syncthreads();
        if (i + 2 < nc) FILL((i + 2) % NSTAGE, (i + 2) * KT);

        const uint32_t sA = smem_base + (i % NSTAGE) * STG_BYTES;
        const uint32_t sB = sA + MAT_BYTES;
#pragma unroll
        for (int kk = 0; kk < KT; kk += 16) {
            uint32_t af[4][4], bB[2][4];
#pragma unroll
            for (int mi = 0; mi < 4; mi++) {
                uint32_t addr = sA
                    + (uint32_t)(wm * 64 + mi * 16 + (lg & 1) * 8 + lt) * RSB
                    + (kk + (lg >> 1) * 8) * 2;
                ldsm4(af[mi], addr);
            }
#pragma unroll
            for (int ni2 = 0; ni2 < 2; ni2++) {
                uint32_t addr = sB
                    + (uint32_t)(wn * 32 + ni2 * 16 + (lg >> 1) * 8 + lt) * RSB
                    + (kk + (lg & 1) * 8) * 2;
                ldsm4(bB[ni2], addr);
            }
#pragma unroll
            for (int mi = 0; mi < 4; mi++)
#pragma unroll
                for (int ni = 0; ni < 4; ni++)
                    mma16816(acc[mi][ni], af[mi], &bB[ni >> 1][(ni & 1) * 2]);
        }
    }
#undef FILL

    if (epi == 4) {
        // qkv scatter: Ch=qp, Ch2=kp, Ch3=vp, Ch4=kpr, Ch5=vpr
#pragma unroll
        for (int mi = 0; mi < 4; mi++) {
#pragma unroll
            for (int half_ = 0; half_ < 2; half_++) {
                int rr = row0 + wm * 64 + mi * 16 + r + half_ * 8;
                if (rr >= M) continue;
                bool main_ = rr < BSC;
                int b = 0, s = 0;
                if (main_) { b = rr / NP; s = rr - b * NP; }
                int sp = rr - BSC;
#pragma unroll
                for (int ni = 0; ni < 4; ni++) {
                    int nc2 = col0 + wn * 32 + ni * 8 + 2 * cg;
                    float v0 = acc[mi][ni][half_ * 2 + 0] + bias[nc2];
                    float v1 = acc[mi][ni][half_ * 2 + 1] + bias[nc2 + 1];
                    __half2 hv = __floats2half2_rn(v0, v1);
                    int p = nc2 / EE, e = nc2 - p * EE;
                    int hh = e >> 6, d = e & 63;
                    if (main_) {
                        __half* pl = (p == 0) ? Ch : (p == 1) ? Ch2 : Ch3;
                        *(__half2*)(pl + ((size_t)(b * NH + hh) * NP + s) * HD + d) = hv;
                    } else if (p >= 1) {
                        __half* pl = (p == 1) ? Ch4 : Ch5;
                        *(__half2*)(pl + (size_t)(hh * NPR + sp) * HD + d) = hv;
                    }
                }
            }
        }
    } else {
#pragma unroll
        for (int mi = 0; mi < 4; mi++) {
            int mr0 = row0 + wm * 64 + mi * 16 + r;
#pragma unroll
            for (int ni = 0; ni < 4; ni++) {
                int nc2 = col0 + wn * 32 + ni * 8 + 2 * cg;
                float b0 = bias[nc2], b1 = bias[nc2 + 1];
#pragma unroll
                for (int half_ = 0; half_ < 2; half_++) {
                    int rr = mr0 + half_ * 8;
                    if (rr >= M) continue;
                    float v0 = acc[mi][ni][half_ * 2 + 0] + b0;
                    float v1 = acc[mi][ni][half_ * 2 + 1] + b1;
                    size_t idx = (size_t)rr * N + nc2;
                    if (epi == 1) {
                        v0 = 0.5f * v0 * (1.f + erff(v0 * 0.70710678118654752f));
                        v1 = 0.5f * v1 * (1.f + erff(v1 * 0.70710678118654752f));
                        *(__half2*)&Ch[idx] = __floats2half2_rn(v0, v1);
                    } else {
                        if (epi == 2) { v0 += Cf[idx]; v1 += Cf[idx + 1]; }
                        Cf[idx] = v0; Cf[idx + 1] = v1;
                    }
                }
            }
        }
    }
}

// ---------------- LN pre (cls/pos assembly; fp32 out, compact) --------------
__global__ void lnpre_kernel(const float* __restrict__ conv, const float* __restrict__ cls,
                             const float* __restrict__ pos, const float* __restrict__ g,
                             const float* __restrict__ bb, float* __restrict__ dst)
{
    int row = blockIdx.x;              // b*NP + s
    int b = row / NP, s = row % NP;
    int t = threadIdx.x;
    const float* base = (s == 0) ? cls : conv + (size_t)(b * NPATCH + s - 1) * EE;
    const float* pr = pos + (size_t)s * EE;
    float x0 = base[t] + pr[t];
    float x1 = base[t + 256] + pr[t + 256];
    float x2 = base[t + 512] + pr[t + 512];
    float mean = blk_sum(x0 + x1 + x2) * (1.f / EE);
    float d0 = x0 - mean, d1 = x1 - mean, d2 = x2 - mean;
    float var = blk_sum(d0 * d0 + d1 * d1 + d2 * d2) * (1.f / EE);
    float rs = rsqrtf(var + EPSV);
    float* o = dst + (size_t)row * EE;
    o[t]       = d0 * rs * g[t]       + bb[t];
    o[t + 256] = d1 * rs * g[t + 256] + bb[t + 256];
    o[t + 512] = d2 * rs * g[t + 512] + bb[t + 512];
}

// ---------------- LN1 warp-per-row fused (compact rows + 16 prompt rows) ----
__global__ __launch_bounds__(256)
void ln1w_kernel(const float* __restrict__ src, const float* __restrict__ prompt,
                 const float* __restrict__ g, const float* __restrict__ bb,
                 __half* __restrict__ dst)
{
    int ww = threadIdx.x >> 5, lane = threadIdx.x & 31;
    int row = blockIdx.x * 8 + ww;            // MQKV = 790*8 exactly
    const float* in = (row < BSC) ? src + (size_t)row * EE
                                  : prompt + (size_t)(row - BSC) * EE;
    float4 v[6];
    float sum = 0.f;
#pragma unroll
    for (int j = 0; j < 6; j++) {
        v[j] = *(const float4*)(in + j * 128 + lane * 4);
        sum += v[j].x + v[j].y + v[j].z + v[j].w;
    }
#pragma unroll
    for (int o = 16; o; o >>= 1) sum += __shfl_xor_sync(0xffffffffu, sum, o);
    float mean = sum * (1.f / EE);
    float var = 0.f;
#pragma unroll
    for (int j = 0; j < 6; j++) {
        float a = v[j].x - mean, b2 = v[j].y - mean;
        float c = v[j].z - mean, d = v[j].w - mean;
        var += a * a + b2 * b2 + c * c + d * d;
    }
#pragma unroll
    for (int o = 16; o; o >>= 1) var += __shfl_xor_sync(0xffffffffu, var, o);
    float rs = rsqrtf(var * (1.f / EE) + EPSV);
    __half* op = dst + (size_t)row * EE;
#pragma unroll
    for (int j = 0; j < 6; j++) {
        int e = j * 128 + lane * 4;
        float4 gv = *(const float4*)(g + e);
        float4 bv = *(const float4*)(bb + e);
        float r0 = (v[j].x - mean) * rs * gv.x + bv.x;
        float r1 = (v[j].y - mean) * rs * gv.y + bv.y;
        float r2 = (v[j].z - mean) * rs * gv.z + bv.z;
        float r3 = (v[j].w - mean) * rs * gv.w + bv.w;
        *(__half2*)(op + e)     = __floats2half2_rn(r0, r1);
        *(__half2*)(op + e + 2) = __floats2half2_rn(r2, r3);
    }
}

// ---------------- LN2 warp-per-row (half out) ----------------
__global__ __launch_bounds__(256)
void lnw_kernel(const float* __restrict__ src, const float* __restrict__ g,
                const float* __restrict__ bb, __half* __restrict__ dst)
{
    int ww = threadIdx.x >> 5, lane = threadIdx.x & 31;
    int row = blockIdx.x * 8 + ww;            // BSC = 788*8 exactly
    const float* in = src + (size_t)row * EE;
    float4 v[6];
    float sum = 0.f;
#pragma unroll
    for (int j = 0; j < 6; j++) {
        v[j] = *(const float4*)(in + j * 128 + lane * 4);
        sum += v[j].x + v[j].y + v[j].z + v[j].w;
    }
#pragma unroll
    for (int o = 16; o; o >>= 1) sum += __shfl_xor_sync(0xffffffffu, sum, o);
    float mean = sum * (1.f / EE);
    float var = 0.f;
#pragma unroll
    for (int j = 0; j < 6; j++) {
        float a = v[j].x - mean, b2 = v[j].y - mean;
        float c = v[j].z - mean, d = v[j].w - mean;
        var += a * a + b2 * b2 + c * c + d * d;
    }
#pragma unroll
    for (int o = 16; o; o >>= 1) var += __shfl_xor_sync(0xffffffffu, var, o);
    float rs = rsqrtf(var * (1.f / EE) + EPSV);
    __half* op = dst + (size_t)row * EE;
#pragma unroll
    for (int j = 0; j < 6; j++) {
        int e = j * 128 + lane * 4;
        float4 gv = *(const float4*)(g + e);
        float4 bv = *(const float4*)(bb + e);
        float r0 = (v[j].x - mean) * rs * gv.x + bv.x;
        float r1 = (v[j].y - mean) * rs * gv.y + bv.y;
        float r2 = (v[j].z - mean) * rs * gv.z + bv.z;
        float r3 = (v[j].w - mean) * rs * gv.w + bv.w;
        *(__half2*)(op + e)     = __floats2half2_rn(r0, r1);
        *(__half2*)(op + e + 2) = __floats2half2_rn(r2, r3);
    }
}

// ---------------- LN post (cls only; fp32 out) ----------------
__global__ void lnpost_kernel(const float* __restrict__ src, const float* __restrict__ g,
                              const float* __restrict__ bb, float* __restrict__ dst)
{
    int b = blockIdx.x;
    int t = threadIdx.x;
    const float* in = src + (size_t)(b * NP) * EE;
    float x0 = in[t], x1 = in[t + 256], x2 = in[t + 512];
    float mean = blk_sum(x0 + x1 + x2) * (1.f / EE);
    float d0 = x0 - mean, d1 = x1 - mean, d2 = x2 - mean;
    float var = blk_sum(d0 * d0 + d1 * d1 + d2 * d2) * (1.f / EE);
    float rs = rsqrtf(var + EPSV);
    float* o = dst + (size_t)b * EE;
    o[t]       = d0 * rs * g[t]       + bb[t];
    o[t + 256] = d1 * rs * g[t + 256] + bb[t + 256];
    o[t + 512] = d2 * rs * g[t + 512] + bb[t + 512];
}

// ---------------- tensor-core flash attention (compact planes) --------------
// smem: Qv/Kv/Vv each [224][72]h (144B rows), then fac/nb [224]f each
#define ATROW 144
#define ATPL  (224 * ATROW)
#define AT_SMEM (3 * ATPL + 224 * 8)

__global__ __launch_bounds__(256)
void attn_kernel(const __half* __restrict__ qp, const __half* __restrict__ kp,
                 const __half* __restrict__ vp, const __half* __restrict__ kpr,
                 const __half* __restrict__ vpr, const float* __restrict__ coeff,
                 __half* __restrict__ outp)
{
    extern __shared__ char smraw[];
    const uint32_t smem_base = (uint32_t)__cvta_generic_to_shared(smraw);
    float* fac = (float*)(smraw + 3 * ATPL);
    float* nb  = fac + 224;

    const int bh = blockIdx.x;
    const int b = bh / NH, h = bh % NH;
    const int tid = threadIdx.x;
    const int w = tid >> 5, lane = tid & 31;
    const int r = lane >> 2, cg = lane & 3;
    const int lg = lane >> 3, lt = lane & 7;

    const size_t bhbase = (size_t)(b * NH + h) * NP * HD;

    if (tid < 224) {
        float f = 0.f, nbv = -1e30f;
        if (tid < NP)      { f = SCALEV; nbv = 0.f; }
        else if (tid < SS) { f = SCALEV * coeff[tid - NP]; nbv = 0.f; }
        fac[tid] = f; nb[tid] = nbv;
    }
    // Q rows 0..207 (zero-fill 197..207)
    for (int idx = tid; idx < 208 * 8; idx += 256) {
        int s = idx >> 3, c = idx & 7;
        cpa16_s(smem_base + s * ATROW + c * 16,
                qp + bhbase + (size_t)s * HD + c * 8, (s < NP) ? 16 : 0);
    }
    // K rows: 0..196 plane, 197..212 prompt, 213..223 zero
    for (int idx = tid; idx < 224 * 8; idx += 256) {
        int s = idx >> 3, c = idx & 7;
        const __half* src; int bytes = 16;
        if (s < NP)      src = kp + bhbase + (size_t)s * HD + c * 8;
        else if (s < SS) src = kpr + (size_t)(h * NPR + (s - NP)) * HD + c * 8;
        else { src = kp; bytes = 0; }
        cpa16_s(smem_base + ATPL + s * ATROW + c * 16, src, bytes);
    }
    // V rows likewise
    for (int idx = tid; idx < 224 * 8; idx += 256) {
        int s = idx >> 3, c = idx & 7;
        const __half* src; int bytes = 16;
        if (s < NP)      src = vp + bhbase + (size_t)s * HD + c * 8;
        else if (s < SS) src = vpr + (size_t)(h * NPR + (s - NP)) * HD + c * 8;
        else { src = vp; bytes = 0; }
        cpa16_s(smem_base + 2 * ATPL + s * ATROW + c * 16, src, bytes);
    }
    asm volatile("cp.async.commit_group;");
    asm volatile("cp.async.wait_group 0;");
    __syncthreads();

    const uint32_t QvU = smem_base;
    const uint32_t KvU = smem_base + ATPL;
    const uint32_t VvU = smem_base + 2 * ATPL;

    for (int q0 = w * 16; q0 < 208; q0 += 128) {
        uint32_t qf[4][4];
#pragma unroll
        for (int ks = 0; ks < 4; ks++)
            ldsm4(qf[ks], QvU + (uint32_t)(q0 + (lg & 1) * 8 + lt) * ATROW
                              + (ks * 16 + (lg >> 1) * 8) * 2);

        float m0 = -INFINITY, m1 = -INFINITY, l0 = 0.f, l1 = 0.f;
        float ao[8][4];
#pragma unroll
        for (int nt = 0; nt < 8; nt++)
#pragma unroll
            for (int e = 0; e < 4; e++) ao[nt][e] = 0.f;

        for (int kt = 0; kt < 14; kt++) {
            float sa[2][4];
#pragma unroll
            for (int ns = 0; ns < 2; ns++)
#pragma unroll
                for (int e = 0; e < 4; e++) sa[ns][e] = 0.f;

#pragma unroll
            for (int ks = 0; ks < 4; ks++) {
                uint32_t bK[4];
                ldsm4(bK, KvU + (uint32_t)(kt * 16 + (lg >> 1) * 8 + lt) * ATROW
                              + (ks * 16 + (lg & 1) * 8) * 2);
                mma16816(sa[0], qf[ks], &bK[0]);
                mma16816(sa[1], qf[ks], &bK[2]);
            }

            float p[2][4];
            float tm0 = -INFINITY, tm1 = -INFINITY;
#pragma unroll
            for (int ns = 0; ns < 2; ns++) {
                int c0 = kt * 16 + ns * 8 + 2 * cg;
                float f0 = fac[c0], f1 = fac[c0 + 1];
                float n0 = nb[c0],  n1 = nb[c0 + 1];
                sa[ns][0] = sa[ns][0] * f0 + n0;
                sa[ns][1] = sa[ns][1] * f1 + n1;
                sa[ns][2] = sa[ns][2] * f0 + n0;
                sa[ns][3] = sa[ns][3] * f1 + n1;
                tm0 = fmaxf(tm0, fmaxf(sa[ns][0], sa[ns][1]));
                tm1 = fmaxf(tm1, fmaxf(sa[ns][2], sa[ns][3]));
            }
#pragma unroll
            for (int o = 1; o <= 2; o <<= 1) {
                tm0 = fmaxf(tm0, __shfl_xor_sync(0xffffffffu, tm0, o));
                tm1 = fmaxf(tm1, __shfl_xor_sync(0xffffffffu, tm1, o));
            }
            float mn0 = fmaxf(m0, tm0), mn1 = fmaxf(m1, tm1);
            float sc0 = __expf(m0 - mn0), sc1 = __expf(m1 - mn1);
            float rs0 = 0.f, rs1 = 0.f;
#pragma unroll
            for (int ns = 0; ns < 2; ns++) {
                p[ns][0] = __expf(sa[ns][0] - mn0);
                p[ns][1] = __expf(sa[ns][1] - mn0);
                p[ns][2] = __expf(sa[ns][2] - mn1);
                p[ns][3] = __expf(sa[ns][3] - mn1);
                rs0 += p[ns][0] + p[ns][1];
                rs1 += p[ns][2] + p[ns][3];
            }
#pragma unroll
            for (int o = 1; o <= 2; o <<= 1) {
                rs0 += __shfl_xor_sync(0xffffffffu, rs0, o);
                rs1 += __shfl_xor_sync(0xffffffffu, rs1, o);
            }
            l0 = l0 * sc0 + rs0; l1 = l1 * sc1 + rs1;
            m0 = mn0; m1 = mn1;

            uint32_t pf[4];
            __half2 ph;
            ph = __floats2half2_rn(p[0][0], p[0][1]); pf[0] = *(uint32_t*)&ph;
            ph = __floats2half2_rn(p[0][2], p[0][3]); pf[1] = *(uint32_t*)&ph;
            ph = __floats2half2_rn(p[1][0], p[1][1]); pf[2] = *(uint32_t*)&ph;
            ph = __floats2half2_rn(p[1][2], p[1][3]); pf[3] = *(uint32_t*)&ph;

#pragma unroll
            for (int nt2 = 0; nt2 < 4; nt2++) {
                uint32_t vf[4];
                ldsm4t(vf, VvU + (uint32_t)(kt * 16 + (lg & 1) * 8 + lt) * ATROW
                               + (nt2 * 16 + (lg >> 1) * 8) * 2);
                int n0 = 2 * nt2, n1 = 2 * nt2 + 1;
                ao[n0][0] *= sc0; ao[n0][1] *= sc0; ao[n0][2] *= sc1; ao[n0][3] *= sc1;
                ao[n1][0] *= sc0; ao[n1][1] *= sc0; ao[n1][2] *= sc1; ao[n1][3] *= sc1;
                mma16816(ao[n0], pf, &vf[0]);
                mma16816(ao[n1], pf, &vf[2]);
            }
        }

        float inv0 = 1.f / l0, inv1 = 1.f / l1;
        int q = q0 + r;
        if (q < NP) {
            __half* orow = outp + (size_t)(b * NP + q) * EE + h * HD;
#pragma unroll
            for (int nt = 0; nt < 8; nt++)
                *(__half2*)&orow[nt * 8 + 2 * cg] =
                    __floats2half2_rn(ao[nt][0] * inv0, ao[nt][1] * inv0);
        }
        int q2 = q0 + 8 + r;
        if (q2 < NP) {
            __half* orow = outp + (size_t)(b * NP + q2) * EE + h * HD;
#pragma unroll
            for (int nt = 0; nt < 8; nt++)
                *(__half2*)&orow[nt * 8 + 2 * cg] =
                    __floats2half2_rn(ao[nt][2] * inv1, ao[nt][3] * inv1);
        }
    }
}

// ---------------- host launch ----------------
extern "C" void kernel_launch(void* const* d_in, const int* in_sizes, int n_in,
                              void* d_out, int out_size)
{
    const float* x        = (const float*)d_in[0];
    const float* coeff    = (const float*)d_in[1];
    const float* patch_w  = (const float*)d_in[2];
    const float* patch_b  = (const float*)d_in[3];
    const float* cls      = (const float*)d_in[4];
    const float* pos      = (const float*)d_in[5];
    const float* lnpre_g  = (const float*)d_in[6];
    const float* lnpre_b  = (const float*)d_in[7];
    const float* prompts  = (const float*)d_in[8];
    const float* ln1_g    = (const float*)d_in[9];
    const float* ln1_b    = (const float*)d_in[10];
    const float* qkv_w    = (const float*)d_in[11];
    const float* qkv_b    = (const float*)d_in[12];
    const float* proj_w   = (const float*)d_in[13];
    const float* proj_b   = (const float*)d_in[14];
    const float* ln2_g    = (const float*)d_in[15];
    const float* ln2_b    = (const float*)d_in[16];
    const float* fc1_w    = (const float*)d_in[17];
    const float* fc1_b    = (const float*)d_in[18];
    const float* fc2_w    = (const float*)d_in[19];
    const float* fc2_b    = (const float*)d_in[20];
    const float* lnpost_g = (const float*)d_in[21];
    const float* lnpost_b = (const float*)d_in[22];
    float* out = (float*)d_out;

    float *p_h, *p_o;
    __half *p_hh, *p_qp, *p_kp, *p_vp, *p_kpr, *p_vpr, *p_oh, *p_ffh;
    __half *p_wq, *p_wp, *p_w1, *p_w2, *p_wc;
    cudaGetSymbolAddress((void**)&p_h,   g_h);
    cudaGetSymbolAddress((void**)&p_hh,  g_hh);
    cudaGetSymbolAddress((void**)&p_qp,  g_qp);
    cudaGetSymbolAddress((void**)&p_kp,  g_kp);
    cudaGetSymbolAddress((void**)&p_vp,  g_vp);
    cudaGetSymbolAddress((void**)&p_kpr, g_kpr);
    cudaGetSymbolAddress((void**)&p_vpr, g_vpr);
    cudaGetSymbolAddress((void**)&p_oh,  g_oh);
    cudaGetSymbolAddress((void**)&p_ffh, g_ffh);
    cudaGetSymbolAddress((void**)&p_o,   g_o);
    cudaGetSymbolAddress((void**)&p_wq,  g_wq);
    cudaGetSymbolAddress((void**)&p_wp,  g_wp);
    cudaGetSymbolAddress((void**)&p_w1,  g_w1);
    cudaGetSymbolAddress((void**)&p_w2,  g_w2);
    cudaGetSymbolAddress((void**)&p_wc,  g_wc);

    cudaFuncSetAttribute(attn_kernel, cudaFuncAttributeMaxDynamicSharedMemorySize, AT_SMEM);
    cudaFuncSetAttribute(hgemm_kernel, cudaFuncAttributeMaxDynamicSharedMemorySize, TG_SMEM);

    {
        int n;
        n = NL * 3 * EE * EE / 4; cvt_kernel<<<(n + 255) / 256, 256>>>(qkv_w,  p_wq, n);
        n = NL * EE * EE / 4;     cvt_kernel<<<(n + 255) / 256, 256>>>(proj_w, p_wp, n);
        n = NL * FFD * EE / 4;    cvt_kernel<<<(n + 255) / 256, 256>>>(fc1_w,  p_w1, n);
        n = NL * EE * FFD / 4;    cvt_kernel<<<(n + 255) / 256, 256>>>(fc2_w,  p_w2, n);
        n = EE * EE / 4;          cvt_kernel<<<(n + 255) / 256, 256>>>(patch_w, p_wc, n);
    }

    im2col_kernel<<<(MCONV * EE + 255) / 256, 256>>>(x, p_ffh);
    hgemm_kernel<<<dim3(EE / 128, MCONV / 128), 256, TG_SMEM>>>(
        p_ffh, p_wc, patch_b, p_o, (__half*)0, (__half*)0, (__half*)0,
        (__half*)0, (__half*)0, MCONV, EE, EE, 0);

    lnpre_kernel<<<BB * NP, 256>>>(p_o, cls, pos, lnpre_g, lnpre_b, p_h);

    const int mt = (MQKV + 127) / 128;   // 50
    for (int l = 0; l < NL; l++) {
        ln1w_kernel<<<MQKV / 8, 256>>>(p_h, prompts + (size_t)l * NPR * EE,
                                       ln1_g + l * EE, ln1_b + l * EE, p_hh);
        hgemm_kernel<<<dim3(3 * EE / 128, mt), 256, TG_SMEM>>>(
            p_hh, p_wq + (size_t)l * 3 * EE * EE, qkv_b + (size_t)l * 3 * EE,
            (float*)0, p_qp, p_kp, p_vp, p_kpr, p_vpr, MQKV, 3 * EE, EE, 4);
        attn_kernel<<<BB * NH, 256, AT_SMEM>>>(p_qp, p_kp, p_vp, p_kpr, p_vpr,
                                               coeff + (size_t)l * NPR, p_oh);
        hgemm_kernel<<<dim3(EE / 128, mt), 256, TG_SMEM>>>(
            p_oh, p_wp + (size_t)l * EE * EE, proj_b + (size_t)l * EE,
            p_h, (__half*)0, (__half*)0, (__half*)0, (__half*)0, (__half*)0,
            BSC, EE, EE, 2);
        lnw_kernel<<<BSC / 8, 256>>>(p_h, ln2_g + l * EE, ln2_b + l * EE, p_hh);
        hgemm_kernel<<<dim3(FFD / 128, mt), 256, TG_SMEM>>>(
            p_hh, p_w1 + (size_t)l * FFD * EE, fc1_b + (size_t)l * FFD,
            (float*)0, p_ffh, (__half*)0, (__half*)0, (__half*)0, (__half*)0,
            BSC, FFD, EE, 1);
        hgemm_kernel<<<dim3(EE / 128, mt), 256, TG_SMEM>>>(
            p_ffh, p_w2 + (size_t)l * EE * FFD, fc2_b + (size_t)l * EE,
            p_h, (__half*)0, (__half*)0, (__half*)0, (__half*)0, (__half*)0,
            BSC, EE, FFD, 2);
    }

    lnpost_kernel<<<BB, 256>>>(p_h, lnpost_g, lnpost_b, out);
}